// round 14
// baseline (speedup 1.0000x reference)
#include <cuda_runtime.h>
#include <cuda_fp16.h>
#include <cstdint>

#define BNUM   4
#define SEQ    512
#define DMODEL 1024
#define HDIM   256
#define MTOT   2048
#define KP2    256       // stage-2 K (pure fp16)
#define NJC    1024      // SEQ * 2 (j,c interleaved)
#define NSPLIT 4         // split-K factor for stage-1 GEMM
#define KSPL   (DMODEL / NSPLIT)   // 256 fp32 k-window per CTA

// Scratch (allocation-free __device__ globals)
__device__ __align__(16) float  g_p1[NSPLIT * MTOT * HDIM];  // 8 MB partials
__device__ __align__(16) __half g_Ap[MTOT * KP2];            // 1 MB
__device__ __align__(16) __half g_Bp[BNUM * NJC * KP2];      // 2 MB

// ---------------------------------------------------------------------------
// helpers
// ---------------------------------------------------------------------------
static __device__ __forceinline__ uint32_t smem_u32(const void* p) {
    uint32_t a;
    asm("{ .reg .u64 t; cvta.to.shared.u64 t, %1; cvt.u32.u64 %0, t; }"
        : "=r"(a) : "l"(p));
    return a;
}
static __device__ __forceinline__ void cp_async16(uint32_t saddr, const void* gaddr) {
    asm volatile("cp.async.cg.shared.global [%0], [%1], 16;"
                 :: "r"(saddr), "l"(gaddr) : "memory");
}
static __device__ __forceinline__ void cp_commit() {
    asm volatile("cp.async.commit_group;" ::: "memory");
}
static __device__ __forceinline__ void cp_wait1() {
    asm volatile("cp.async.wait_group 1;" ::: "memory");
}
static __device__ __forceinline__ void cp_wait0() {
    asm volatile("cp.async.wait_group 0;" ::: "memory");
}
static __device__ __forceinline__ void ldsm_x4(uint32_t* r, uint32_t addr) {
    asm volatile("ldmatrix.sync.aligned.m8n8.x4.shared.b16 {%0,%1,%2,%3}, [%4];"
                 : "=r"(r[0]), "=r"(r[1]), "=r"(r[2]), "=r"(r[3]) : "r"(addr));
}
static __device__ __forceinline__ void mma16816(float* d, const uint32_t* a,
                                                uint32_t b0, uint32_t b1) {
    asm volatile(
        "mma.sync.aligned.m16n8k16.row.col.f32.f16.f16.f32 "
        "{%0,%1,%2,%3}, {%4,%5,%6,%7}, {%8,%9}, {%0,%1,%2,%3};"
        : "+f"(d[0]), "+f"(d[1]), "+f"(d[2]), "+f"(d[3])
        : "r"(a[0]), "r"(a[1]), "r"(a[2]), "r"(a[3]), "r"(b0), "r"(b1));
}
static __device__ __forceinline__ void st_h2(__half* p, __half a, __half b) {
    __half2 t; t.x = a; t.y = b;
    *(__half2*)p = t;
}
static __device__ __forceinline__ uint32_t pack_h2(float a, float b) {
    __half2 h = __floats2half2_rn(a, b);
    return *(uint32_t*)&h;
}

// ---------------------------------------------------------------------------
// Prep (fused reduce): o = sum_s p1[s] + b1; A' = o (fp16);
// B' rows jc=2j+c: v = o * w_c (fp16)
// ---------------------------------------------------------------------------
__global__ __launch_bounds__(256) void prep_o(const float* __restrict__ W2,
                                              const float* __restrict__ b1) {
    int idx = blockIdx.x * 256 + threadIdx.x;       // over 2048*64
    int m = idx >> 6;
    int h = (idx & 63) * 4;

    float4 o4 = *(const float4*)(g_p1 + (size_t)m * HDIM + h);
#pragma unroll
    for (int s = 1; s < NSPLIT; ++s) {
        float4 p = *(const float4*)(g_p1 + ((size_t)s * MTOT + m) * HDIM + h);
        o4.x += p.x; o4.y += p.y; o4.z += p.z; o4.w += p.w;
    }
    float4 bb = *(const float4*)(b1 + h);
    o4.x += bb.x; o4.y += bb.y; o4.z += bb.z; o4.w += bb.w;

    __half* abase = g_Ap + (size_t)m * KP2 + h;
    st_h2(abase,     __float2half_rn(o4.x), __float2half_rn(o4.y));
    st_h2(abase + 2, __float2half_rn(o4.z), __float2half_rn(o4.w));

    int b = m >> 9, j = m & 511;
    float4 w0 = *(const float4*)(W2 + h);
    float4 w1 = *(const float4*)(W2 + HDIM + h);
#pragma unroll
    for (int c = 0; c < 2; ++c) {
        float4 w = c ? w1 : w0;
        __half* bbase = g_Bp + ((size_t)b * NJC + 2 * j + c) * KP2 + h;
        st_h2(bbase,     __float2half_rn(o4.x * w.x), __float2half_rn(o4.y * w.y));
        st_h2(bbase + 2, __float2half_rn(o4.z * w.z), __float2half_rn(o4.w * w.w));
    }
}

// ---------------------------------------------------------------------------
// GEMM 1 (fused fp32->fp16 convert): p1[z][m,h] = sum_k X[m,k] W1[h,k],
// k-window z*256..+256. CTA tile 64x64, BK=32, NC=8, double-buffered
// reg-staged loader (LDG fp32 -> cvt -> STS fp16). 256 thr / 8 warps,
// in-CTA k16-split (grp = wid>>2), combined via smem epilogue.
// smem tile rows 64B; XOR swizzle 16B chunk ^= (row>>1)&3.
// ---------------------------------------------------------------------------
#define G1_NC   8
#define G1_BUF  8192                  // one buffer: A 4KB + B 4KB
#define SMEM1   17408                 // max(2 buffers 16KB, sC 64*66*4=16.9KB)
#define SDP  66                       // fp32 combine-tile pitch

__global__ __launch_bounds__(256, 3) void gemm1_kernel(const float* __restrict__ X,
                                                       const float* __restrict__ W1) {
    extern __shared__ char smem[];
    const uint32_t sbase = smem_u32(smem);
    const int tid = threadIdx.x;
    const int wid = tid >> 5, lane = tid & 31;
    const int grp = wid >> 2;
    const int wm = wid & 1, wn = (wid >> 1) & 1;
    const int m0 = blockIdx.y * 64, n0 = blockIdx.x * 64;
    const int kw = blockIdx.z * KSPL;

    // loader mapping: row = tid>>2 (0..63), c16 = tid&3 (16B fp16 chunk = 8 elems)
    const int lrow = tid >> 2;
    const int lc16 = tid & 3;
    const uint32_t stsOff = (uint32_t)(lrow * 64)
                          + (uint32_t)((lc16 ^ ((lrow >> 1) & 3)) << 4);
    const float* Ag = X  + (size_t)(m0 + lrow) * DMODEL + kw + lc16 * 8;
    const float* Bg = W1 + (size_t)(n0 + lrow) * DMODEL + kw + lc16 * 8;

    float acc[2][4][4];
#pragma unroll
    for (int mt = 0; mt < 2; ++mt)
#pragma unroll
        for (int j = 0; j < 4; ++j)
#pragma unroll
            for (int e = 0; e < 4; ++e) acc[mt][j][e] = 0.0f;

    // prologue: stage 0
    {
        float4 a0 = *(const float4*)(Ag);
        float4 a1 = *(const float4*)(Ag + 4);
        float4 b0 = *(const float4*)(Bg);
        float4 b1 = *(const float4*)(Bg + 4);
        uint4 pa; pa.x = pack_h2(a0.x, a0.y); pa.y = pack_h2(a0.z, a0.w);
                  pa.z = pack_h2(a1.x, a1.y); pa.w = pack_h2(a1.z, a1.w);
        uint4 pb; pb.x = pack_h2(b0.x, b0.y); pb.y = pack_h2(b0.z, b0.w);
                  pb.z = pack_h2(b1.x, b1.y); pb.w = pack_h2(b1.z, b1.w);
        *(uint4*)(smem + stsOff)        = pa;
        *(uint4*)(smem + 4096 + stsOff) = pb;
    }
    __syncthreads();

    // fragment addresses (rows +16 share the same swizzle key)
    const int arow = wm * 32 + (lane & 15);
    const int brow = wn * 32 + (lane & 15);
    const int kl   = lane >> 4;
    const int c16f = grp * 2 + kl;
    const uint32_t aOff = (uint32_t)(arow * 64)
                        + (uint32_t)((c16f ^ ((arow >> 1) & 3)) << 4);
    const uint32_t bOff = 4096u + (uint32_t)(brow * 64)
                        + (uint32_t)((c16f ^ ((brow >> 1) & 3)) << 4);

    for (int kc = 0; kc < G1_NC; ++kc) {
        float4 na0, na1, nb0, nb1;
        const bool more = (kc + 1 < G1_NC);
        if (more) {
            const float* An = Ag + (kc + 1) * 32;
            const float* Bn = Bg + (kc + 1) * 32;
            na0 = *(const float4*)(An);
            na1 = *(const float4*)(An + 4);
            nb0 = *(const float4*)(Bn);
            nb1 = *(const float4*)(Bn + 4);
        }

        const uint32_t buf = sbase + (uint32_t)((kc & 1) * G1_BUF);
        uint32_t a0[4], a1[4], b0[4], b1[4];
        ldsm_x4(a0, buf + aOff);
        ldsm_x4(a1, buf + aOff + 16 * 64);
        ldsm_x4(b0, buf + bOff);
        ldsm_x4(b1, buf + bOff + 16 * 64);
        mma16816(acc[0][0], a0, b0[0], b0[2]);
        mma16816(acc[0][1], a0, b0[1], b0[3]);
        mma16816(acc[0][2], a0, b1[0], b1[2]);
        mma16816(acc[0][3], a0, b1[1], b1[3]);
        mma16816(acc[1][0], a1, b0[0], b0[2]);
        mma16816(acc[1][1], a1, b0[1], b0[3]);
        mma16816(acc[1][2], a1, b1[0], b1[2]);
        mma16816(acc[1][3], a1, b1[1], b1[3]);

        if (more) {
            const uint32_t nb = (uint32_t)(((kc + 1) & 1) * G1_BUF);
            uint4 pa; pa.x = pack_h2(na0.x, na0.y); pa.y = pack_h2(na0.z, na0.w);
                      pa.z = pack_h2(na1.x, na1.y); pa.w = pack_h2(na1.z, na1.w);
            uint4 pb; pb.x = pack_h2(nb0.x, nb0.y); pb.y = pack_h2(nb0.z, nb0.w);
                      pb.z = pack_h2(nb1.x, nb1.y); pb.w = pack_h2(nb1.z, nb1.w);
            *(uint4*)(smem + nb + stsOff)        = pa;
            *(uint4*)(smem + nb + 4096 + stsOff) = pb;
        }
        __syncthreads();
    }

    // combine k-groups via smem, store to g_p1
    float* sC = (float*)smem;
    const int rr = lane >> 2;
    const int cc0 = wn * 32 + (lane & 3) * 2;

    if (grp == 1) {
#pragma unroll
        for (int mt = 0; mt < 2; ++mt)
#pragma unroll
            for (int j = 0; j < 4; ++j) {
                const int r0 = wm * 32 + rr + mt * 16;
                const int c  = cc0 + j * 8;
                float2 v0; v0.x = acc[mt][j][0]; v0.y = acc[mt][j][1];
                float2 v1; v1.x = acc[mt][j][2]; v1.y = acc[mt][j][3];
                *(float2*)(sC + r0 * SDP + c)       = v0;
                *(float2*)(sC + (r0 + 8) * SDP + c) = v1;
            }
    }
    __syncthreads();
    if (grp == 0) {
        const int row0 = m0 + wm * 32 + rr;
        const int col0 = n0 + cc0;
        float* base = g_p1 + (size_t)blockIdx.z * MTOT * HDIM;
#pragma unroll
        for (int mt = 0; mt < 2; ++mt) {
#pragma unroll
            for (int j = 0; j < 4; ++j) {
                const int lr0 = wm * 32 + rr + mt * 16;
                const int lc2 = cc0 + j * 8;
                float2 p0 = *(float2*)(sC + lr0 * SDP + lc2);
                float2 p1 = *(float2*)(sC + (lr0 + 8) * SDP + lc2);
                const int col = col0 + j * 8;
                const int r0 = row0 + mt * 16;
                float2 v0; v0.x = acc[mt][j][0] + p0.x; v0.y = acc[mt][j][1] + p0.y;
                float2 v1; v1.x = acc[mt][j][2] + p1.x; v1.y = acc[mt][j][3] + p1.y;
                *(float2*)(base + (size_t)r0 * HDIM + col)       = v0;
                *(float2*)(base + (size_t)(r0 + 8) * HDIM + col) = v1;
            }
        }
    }
}

// ---------------------------------------------------------------------------
// GEMM 2: mma.sync fp16 TN, D[64,64], BK=64, 3-stage cp.async pipeline,
// TRIANGULAR grid (2, 36, 4): blockIdx.y = pair (it<=jt), blockIdx.x = jc
// half. NC=4; off-diagonal pairs also write the mirrored tile out[b,j,i,c].
// ---------------------------------------------------------------------------
#define BK   64
#define ASB  8192                     // stage bytes (A or B): 64 rows * 128B
#define BOFFB (3 * ASB)               // B region offset: 24576
#define SMEM_SZ (6 * ASB)             // 49152 bytes == default 48KB limit
#define G2_NC (KP2 / BK)              // 4

__global__ __launch_bounds__(256, 4) void gemm2_kernel(const float* __restrict__ bias,
                                                       float* __restrict__ outp) {
    extern __shared__ char smem[];
    const uint32_t sbase = smem_u32(smem);
    const int tid = threadIdx.x;
    const int wid = tid >> 5, lane = tid & 31;
    const int grp = wid >> 2;
    const int wm = wid & 1, wn = (wid >> 1) & 1;
    const int bz = blockIdx.z;

    const int half = blockIdx.x;
    int p = blockIdx.y;                              // 0..35
    int jt = 0;
    while (((jt + 1) * (jt + 2) >> 1) <= p) ++jt;
    const int it = p - ((jt * (jt + 1)) >> 1);
    const int m0 = it * 64;
    const int n0 = jt * 128 + half * 64;

    const __half* Ab = g_Ap + ((size_t)(bz * SEQ + m0)) * KP2;
    const __half* Bb = g_Bp + ((size_t)(bz * NJC + n0)) * KP2;

    const int lrow = tid >> 2;
    const int lcb  = (tid & 3) * 2;
    const int lxr  = lrow & 7;

    float acc[2][4][4];
#pragma unroll
    for (int mt = 0; mt < 2; ++mt)
#pragma unroll
        for (int j = 0; j < 4; ++j)
#pragma unroll
            for (int e = 0; e < 4; ++e) acc[mt][j][e] = 0.0f;

#pragma unroll
    for (int s = 0; s < 2; ++s) {
        const __half* Ag = Ab + s * BK + (size_t)lrow * KP2 + lcb * 8;
        const __half* Bg = Bb + s * BK + (size_t)lrow * KP2 + lcb * 8;
        const uint32_t rowA = sbase + s * ASB + lrow * 128;
        const uint32_t rowB = rowA + BOFFB;
#pragma unroll
        for (int q = 0; q < 2; ++q) {
            const uint32_t sw = (uint32_t)(((lcb + q) ^ lxr) << 4);
            cp_async16(rowA + sw, Ag + q * 8);
            cp_async16(rowB + sw, Bg + q * 8);
        }
        cp_commit();
    }

    const int arow = wm * 32 + (lane & 15);
    const int brow = wn * 32 + (lane & 15);
    const int kl   = lane >> 4;
    const uint32_t aRow = sbase + (uint32_t)(arow * 128);
    const uint32_t bRow = sbase + BOFFB + (uint32_t)(brow * 128);
    const int axr = arow & 7, bxr = brow & 7;

    for (int kc = 0; kc < G2_NC; ++kc) {
        cp_wait1();
        __syncthreads();

        const int s = kc % 3;
        const uint32_t aS = aRow + (uint32_t)(s * ASB);
        const uint32_t bS = bRow + (uint32_t)(s * ASB);
#pragma unroll
        for (int ksi = 0; ksi < 2; ++ksi) {
            const int c16 = (grp * 2 + ksi) * 2 + kl;
            const uint32_t swa = (uint32_t)((c16 ^ axr) << 4);
            const uint32_t swb = (uint32_t)((c16 ^ bxr) << 4);
            uint32_t a0[4], a1[4], b0[4], b1[4];
            ldsm_x4(a0, aS + swa);
            ldsm_x4(a1, aS + 16 * 128 + swa);
            ldsm_x4(b0, bS + swb);
            ldsm_x4(b1, bS + 16 * 128 + swb);
            mma16816(acc[0][0], a0, b0[0], b0[2]);
            mma16816(acc[0][1], a0, b0[1], b0[3]);
            mma16816(acc[0][2], a0, b1[0], b1[2]);
            mma16816(acc[0][3], a0, b1[1], b1[3]);
            mma16816(acc[1][0], a1, b0[0], b0[2]);
            mma16816(acc[1][1], a1, b0[1], b0[3]);
            mma16816(acc[1][2], a1, b1[0], b1[2]);
            mma16816(acc[1][3], a1, b1[1], b1[3]);
        }

        if (kc + 2 < G2_NC) {
            const int s2 = (kc + 2) % 3;
            const __half* Ag = Ab + (kc + 2) * BK + (size_t)lrow * KP2 + lcb * 8;
            const __half* Bg = Bb + (kc + 2) * BK + (size_t)lrow * KP2 + lcb * 8;
            const uint32_t rowA = sbase + s2 * ASB + lrow * 128;
            const uint32_t rowB = rowA + BOFFB;
#pragma unroll
            for (int q = 0; q < 2; ++q) {
                const uint32_t sw = (uint32_t)(((lcb + q) ^ lxr) << 4);
                cp_async16(rowA + sw, Ag + q * 8);
                cp_async16(rowB + sw, Bg + q * 8);
            }
        }
        cp_commit();
    }

    cp_wait0();
    __syncthreads();

    float* sC = (float*)smem;
    const int rr = lane >> 2;
    const int cc0 = wn * 32 + (lane & 3) * 2;

    if (grp == 1) {
#pragma unroll
        for (int mt = 0; mt < 2; ++mt)
#pragma unroll
            for (int j = 0; j < 4; ++j) {
                const int r0 = wm * 32 + rr + mt * 16;
                const int c  = cc0 + j * 8;
                float2 v0; v0.x = acc[mt][j][0]; v0.y = acc[mt][j][1];
                float2 v1; v1.x = acc[mt][j][2]; v1.y = acc[mt][j][3];
                *(float2*)(sC + r0 * SDP + c)       = v0;
                *(float2*)(sC + (r0 + 8) * SDP + c) = v1;
            }
    }
    __syncthreads();
    if (grp == 0) {
#pragma unroll
        for (int mt = 0; mt < 2; ++mt)
#pragma unroll
            for (int j = 0; j < 4; ++j) {
                const int r0 = wm * 32 + rr + mt * 16;
                const int c  = cc0 + j * 8;
                float2 p0 = *(float2*)(sC + r0 * SDP + c);
                float2 p1 = *(float2*)(sC + (r0 + 8) * SDP + c);
                p0.x += acc[mt][j][0]; p0.y += acc[mt][j][1];
                p1.x += acc[mt][j][2]; p1.y += acc[mt][j][3];
                *(float2*)(sC + r0 * SDP + c)       = p0;
                *(float2*)(sC + (r0 + 8) * SDP + c) = p1;
            }
    }
    __syncthreads();

    const float bv0 = bias[0], bv1 = bias[1];
    {
        const int r  = tid >> 2;
        const int cb = (tid & 3) * 16;
        float* dbase = outp + ((size_t)(bz * SEQ + m0 + r)) * NJC + n0;
#pragma unroll
        for (int e = 0; e < 8; ++e) {
            const int col = cb + e * 2;
            float2 v;
            v.x = sC[r * SDP + col] + bv0;
            v.y = sC[r * SDP + col + 1] + bv1;
            *(float2*)(dbase + col) = v;
        }
    }
    if (it != jt) {
        const int jl = tid >> 3;
        const int ql = tid & 7;
        const int j  = jt * 64 + half * 32 + jl;
        float* mbase = outp + ((size_t)(bz * SEQ + j)) * NJC + 2 * m0;
#pragma unroll
        for (int e = 0; e < 8; ++e) {
            const int q = ql + 8 * e;
            float2 s = *(float2*)(sC + q * SDP + 2 * jl);
            float2 v;
            v.x = s.x + bv0;
            v.y = s.y + bv1;
            *(float2*)(mbase + 2 * q) = v;
        }
    }
}

// ---------------------------------------------------------------------------
extern "C" void kernel_launch(void* const* d_in, const int* in_sizes, int n_in,
                              void* d_out, int out_size)
{
    const float* x  = (const float*)d_in[0];   // [4, 512, 1024]
    const float* W1 = (const float*)d_in[1];   // [256, 1024]
    const float* b1 = (const float*)d_in[2];   // [256]
    const float* W2 = (const float*)d_in[3];   // [2, 256]
    const float* b2 = (const float*)d_in[4];   // [2]
    float* out = (float*)d_out;                // [4, 512, 512, 2]

    // Stage 1 GEMM (fused fp32->fp16 convert, split-K=4)
    gemm1_kernel<<<dim3(HDIM / 64, MTOT / 64, NSPLIT), 256, SMEM1>>>(x, W1);

    // Prep: fused reduce(+b1) + convert + fold W2 into B operand
    prep_o<<<512, 256>>>(W2, b1);

    // Stage 2 GEMM (triangular): 36 pairs x 2 jc-halves x 4 batches = 288 CTAs
    gemm2_kernel<<<dim3(2, 36, BNUM), 256, SMEM_SZ>>>(b2, out);
}

// round 15
// speedup vs baseline: 1.1892x; 1.1892x over previous
#include <cuda_runtime.h>
#include <cuda_fp16.h>
#include <cstdint>

#define BNUM   4
#define SEQ    512
#define DMODEL 1024
#define HDIM   256
#define MTOT   2048
#define KP2    256       // stage-2 K (pure fp16)
#define NJC    1024      // SEQ * 2 (j,c interleaved)

// Scratch (allocation-free __device__ globals)
__device__ __align__(16) __half g_Xp[MTOT * DMODEL];         // 4 MB
__device__ __align__(16) __half g_W1p[HDIM * DMODEL];        // 0.5 MB
__device__ __align__(16) __half g_Ap[MTOT * KP2];            // 1 MB
__device__ __align__(16) __half g_Bp[BNUM * NJC * KP2];      // 2 MB

// ---------------------------------------------------------------------------
// helpers
// ---------------------------------------------------------------------------
static __device__ __forceinline__ uint32_t smem_u32(const void* p) {
    uint32_t a;
    asm("{ .reg .u64 t; cvta.to.shared.u64 t, %1; cvt.u32.u64 %0, t; }"
        : "=r"(a) : "l"(p));
    return a;
}
static __device__ __forceinline__ void cp_async16(uint32_t saddr, const void* gaddr) {
    asm volatile("cp.async.cg.shared.global [%0], [%1], 16;"
                 :: "r"(saddr), "l"(gaddr) : "memory");
}
static __device__ __forceinline__ void cp_commit() {
    asm volatile("cp.async.commit_group;" ::: "memory");
}
static __device__ __forceinline__ void cp_wait1() {
    asm volatile("cp.async.wait_group 1;" ::: "memory");
}
static __device__ __forceinline__ void cp_wait0() {
    asm volatile("cp.async.wait_group 0;" ::: "memory");
}
static __device__ __forceinline__ void ldsm_x4(uint32_t* r, uint32_t addr) {
    asm volatile("ldmatrix.sync.aligned.m8n8.x4.shared.b16 {%0,%1,%2,%3}, [%4];"
                 : "=r"(r[0]), "=r"(r[1]), "=r"(r[2]), "=r"(r[3]) : "r"(addr));
}
static __device__ __forceinline__ void mma16816(float* d, const uint32_t* a,
                                                uint32_t b0, uint32_t b1) {
    asm volatile(
        "mma.sync.aligned.m16n8k16.row.col.f32.f16.f16.f32 "
        "{%0,%1,%2,%3}, {%4,%5,%6,%7}, {%8,%9}, {%0,%1,%2,%3};"
        : "+f"(d[0]), "+f"(d[1]), "+f"(d[2]), "+f"(d[3])
        : "r"(a[0]), "r"(a[1]), "r"(a[2]), "r"(a[3]), "r"(b0), "r"(b1));
}
static __device__ __forceinline__ void st_h2(__half* p, __half a, __half b) {
    __half2 t; t.x = a; t.y = b;
    *(__half2*)p = t;
}
static __device__ __forceinline__ void st_h2f(__half* p, float a, float b) {
    __half2 t = __floats2half2_rn(a, b);
    *(__half2*)p = t;
}

// ---------------------------------------------------------------------------
// Prep 1: straight fp32 -> fp16 convert of X and W1
// ---------------------------------------------------------------------------
__global__ __launch_bounds__(256) void split_xw(const float* __restrict__ X,
                                                const float* __restrict__ W1) {
    const int NX4 = MTOT * DMODEL / 4;   // 524288
    int idx = blockIdx.x * 256 + threadIdx.x;
    if (idx < NX4) {
        int r = idx >> 8;
        int k = (idx & 255) * 4;
        float4 v = *(const float4*)(X + (size_t)r * DMODEL + k);
        __half* base = g_Xp + (size_t)r * DMODEL + k;
        st_h2(base,     __float2half_rn(v.x), __float2half_rn(v.y));
        st_h2(base + 2, __float2half_rn(v.z), __float2half_rn(v.w));
    } else {
        int i2 = idx - NX4;
        if (i2 >= HDIM * DMODEL / 4) return;
        int r = i2 >> 8;
        int k = (i2 & 255) * 4;
        float4 v = *(const float4*)(W1 + (size_t)r * DMODEL + k);
        __half* base = g_W1p + (size_t)r * DMODEL + k;
        st_h2(base,     __float2half_rn(v.x), __float2half_rn(v.y));
        st_h2(base + 2, __float2half_rn(v.z), __float2half_rn(v.w));
    }
}

// ---------------------------------------------------------------------------
// common tiling constants
// ---------------------------------------------------------------------------
#define BK   64
#define ASB  8192                     // stage bytes (A or B): 64 rows * 128B
#define BOFFB (3 * ASB)               // B region offset: 24576
#define SMEM_SZ (6 * ASB)             // 49152 bytes == default 48KB limit
#define SDP  66                       // fp32 combine-tile pitch

// ---------------------------------------------------------------------------
// GEMM 1 (full K, fused epilogue): o[m, n0+..] = X[m,:] @ W1[n,:]^T + b1;
// writes g_Ap = h(o) and g_Bp rows 2j+c = h(o * w_c). Grid (4, 32), NC=16.
// 256 thr / 8 warps, in-CTA k16-split (grp), full-tile smem combine.
// ---------------------------------------------------------------------------
__global__ __launch_bounds__(256, 4) void gemm1_kernel(const float* __restrict__ W2,
                                                       const float* __restrict__ b1) {
    extern __shared__ char smem[];
    const uint32_t sbase = smem_u32(smem);
    const int tid = threadIdx.x;
    const int wid = tid >> 5, lane = tid & 31;
    const int grp = wid >> 2;
    const int wm = wid & 1, wn = (wid >> 1) & 1;
    const int m0 = blockIdx.y * 64, n0 = blockIdx.x * 64;

    const __half* Ab = g_Xp + (size_t)m0 * DMODEL;
    const __half* Bb = g_W1p + (size_t)n0 * DMODEL;
    const int nc = DMODEL / BK;                      // 16

    const int lrow = tid >> 2;
    const int lcb  = (tid & 3) * 2;
    const int lxr  = lrow & 7;

    float acc[2][4][4];
#pragma unroll
    for (int mt = 0; mt < 2; ++mt)
#pragma unroll
        for (int j = 0; j < 4; ++j)
#pragma unroll
            for (int e = 0; e < 4; ++e) acc[mt][j][e] = 0.0f;

#pragma unroll
    for (int s = 0; s < 2; ++s) {
        const __half* Ag = Ab + s * BK + (size_t)lrow * DMODEL + lcb * 8;
        const __half* Bg = Bb + s * BK + (size_t)lrow * DMODEL + lcb * 8;
        const uint32_t rowA = sbase + s * ASB + lrow * 128;
        const uint32_t rowB = rowA + BOFFB;
#pragma unroll
        for (int q = 0; q < 2; ++q) {
            const uint32_t sw = (uint32_t)(((lcb + q) ^ lxr) << 4);
            cp_async16(rowA + sw, Ag + q * 8);
            cp_async16(rowB + sw, Bg + q * 8);
        }
        cp_commit();
    }

    const int arow = wm * 32 + (lane & 15);
    const int brow = wn * 32 + (lane & 15);
    const int kl   = lane >> 4;
    const uint32_t aRow = sbase + (uint32_t)(arow * 128);
    const uint32_t bRow = sbase + BOFFB + (uint32_t)(brow * 128);
    const int axr = arow & 7, bxr = brow & 7;

    for (int kc = 0; kc < nc; ++kc) {
        cp_wait1();
        __syncthreads();

        const int s = kc % 3;
        const uint32_t aS = aRow + (uint32_t)(s * ASB);
        const uint32_t bS = bRow + (uint32_t)(s * ASB);
#pragma unroll
        for (int ksi = 0; ksi < 2; ++ksi) {
            const int c16 = (grp * 2 + ksi) * 2 + kl;
            const uint32_t swa = (uint32_t)((c16 ^ axr) << 4);
            const uint32_t swb = (uint32_t)((c16 ^ bxr) << 4);
            uint32_t a0[4], a1[4], b0[4], b1r[4];
            ldsm_x4(a0, aS + swa);
            ldsm_x4(a1, aS + 16 * 128 + swa);
            ldsm_x4(b0, bS + swb);
            ldsm_x4(b1r, bS + 16 * 128 + swb);
            mma16816(acc[0][0], a0, b0[0], b0[2]);
            mma16816(acc[0][1], a0, b0[1], b0[3]);
            mma16816(acc[0][2], a0, b1r[0], b1r[2]);
            mma16816(acc[0][3], a0, b1r[1], b1r[3]);
            mma16816(acc[1][0], a1, b0[0], b0[2]);
            mma16816(acc[1][1], a1, b0[1], b0[3]);
            mma16816(acc[1][2], a1, b1r[0], b1r[2]);
            mma16816(acc[1][3], a1, b1r[1], b1r[3]);
        }

        if (kc + 2 < nc) {
            const int s2 = (kc + 2) % 3;
            const __half* Ag = Ab + (kc + 2) * BK + (size_t)lrow * DMODEL + lcb * 8;
            const __half* Bg = Bb + (kc + 2) * BK + (size_t)lrow * DMODEL + lcb * 8;
            const uint32_t rowA = sbase + s2 * ASB + lrow * 128;
            const uint32_t rowB = rowA + BOFFB;
#pragma unroll
            for (int q = 0; q < 2; ++q) {
                const uint32_t sw = (uint32_t)(((lcb + q) ^ lxr) << 4);
                cp_async16(rowA + sw, Ag + q * 8);
                cp_async16(rowB + sw, Bg + q * 8);
            }
        }
        cp_commit();
    }

    // combine both k-groups into full fp32 tile in smem
    cp_wait0();
    __syncthreads();
    float* sC = (float*)smem;
    const int rr = lane >> 2;
    const int cc0 = wn * 32 + (lane & 3) * 2;

    if (grp == 1) {
#pragma unroll
        for (int mt = 0; mt < 2; ++mt)
#pragma unroll
            for (int j = 0; j < 4; ++j) {
                const int r0 = wm * 32 + rr + mt * 16;
                const int c  = cc0 + j * 8;
                float2 v0; v0.x = acc[mt][j][0]; v0.y = acc[mt][j][1];
                float2 v1; v1.x = acc[mt][j][2]; v1.y = acc[mt][j][3];
                *(float2*)(sC + r0 * SDP + c)       = v0;
                *(float2*)(sC + (r0 + 8) * SDP + c) = v1;
            }
    }
    __syncthreads();
    if (grp == 0) {
#pragma unroll
        for (int mt = 0; mt < 2; ++mt)
#pragma unroll
            for (int j = 0; j < 4; ++j) {
                const int r0 = wm * 32 + rr + mt * 16;
                const int c  = cc0 + j * 8;
                float2 p0 = *(float2*)(sC + r0 * SDP + c);
                float2 p1 = *(float2*)(sC + (r0 + 8) * SDP + c);
                p0.x += acc[mt][j][0]; p0.y += acc[mt][j][1];
                p1.x += acc[mt][j][2]; p1.y += acc[mt][j][3];
                *(float2*)(sC + r0 * SDP + c)       = p0;
                *(float2*)(sC + (r0 + 8) * SDP + c) = p1;
            }
    }
    __syncthreads();

    // fused epilogue: o = sC + b1; write g_Ap (fp16) and g_Bp rows (o*w0, o*w1)
    {
        const int r  = tid >> 2;                     // 0..63
        const int cb = (tid & 3) * 16;               // 16 cols each
        const int m  = m0 + r;
        const int b  = m >> 9, j = m & 511;
        __half* ap  = g_Ap + (size_t)m * KP2 + n0;
        __half* bp0 = g_Bp + ((size_t)b * NJC + 2 * j) * KP2 + n0;
        __half* bp1 = bp0 + KP2;
#pragma unroll
        for (int e = 0; e < 8; ++e) {
            const int col = cb + e * 2;
            const float o0 = sC[r * SDP + col]     + b1[n0 + col];
            const float o1 = sC[r * SDP + col + 1] + b1[n0 + col + 1];
            const float w00 = W2[n0 + col],        w01 = W2[n0 + col + 1];
            const float w10 = W2[HDIM + n0 + col], w11 = W2[HDIM + n0 + col + 1];
            st_h2f(ap  + col, o0,       o1);
            st_h2f(bp0 + col, o0 * w00, o1 * w01);
            st_h2f(bp1 + col, o0 * w10, o1 * w11);
        }
    }
}

// ---------------------------------------------------------------------------
// GEMM 2: mma.sync fp16 TN, D[64,64], BK=64, NC=4, 3-stage cp.async pipeline,
// TRIANGULAR grid (2, 36, 4); off-diagonal pairs also write mirrored tile.
// ---------------------------------------------------------------------------
#define G2_NC (KP2 / BK)              // 4

__global__ __launch_bounds__(256, 4) void gemm2_kernel(const float* __restrict__ bias,
                                                       float* __restrict__ outp) {
    extern __shared__ char smem[];
    const uint32_t sbase = smem_u32(smem);
    const int tid = threadIdx.x;
    const int wid = tid >> 5, lane = tid & 31;
    const int grp = wid >> 2;
    const int wm = wid & 1, wn = (wid >> 1) & 1;
    const int bz = blockIdx.z;

    const int half = blockIdx.x;
    int p = blockIdx.y;
    int jt = 0;
    while (((jt + 1) * (jt + 2) >> 1) <= p) ++jt;
    const int it = p - ((jt * (jt + 1)) >> 1);
    const int m0 = it * 64;
    const int n0 = jt * 128 + half * 64;

    const __half* Ab = g_Ap + ((size_t)(bz * SEQ + m0)) * KP2;
    const __half* Bb = g_Bp + ((size_t)(bz * NJC + n0)) * KP2;

    const int lrow = tid >> 2;
    const int lcb  = (tid & 3) * 2;
    const int lxr  = lrow & 7;

    float acc[2][4][4];
#pragma unroll
    for (int mt = 0; mt < 2; ++mt)
#pragma unroll
        for (int j = 0; j < 4; ++j)
#pragma unroll
            for (int e = 0; e < 4; ++e) acc[mt][j][e] = 0.0f;

#pragma unroll
    for (int s = 0; s < 2; ++s) {
        const __half* Ag = Ab + s * BK + (size_t)lrow * KP2 + lcb * 8;
        const __half* Bg = Bb + s * BK + (size_t)lrow * KP2 + lcb * 8;
        const uint32_t rowA = sbase + s * ASB + lrow * 128;
        const uint32_t rowB = rowA + BOFFB;
#pragma unroll
        for (int q = 0; q < 2; ++q) {
            const uint32_t sw = (uint32_t)(((lcb + q) ^ lxr) << 4);
            cp_async16(rowA + sw, Ag + q * 8);
            cp_async16(rowB + sw, Bg + q * 8);
        }
        cp_commit();
    }

    const int arow = wm * 32 + (lane & 15);
    const int brow = wn * 32 + (lane & 15);
    const int kl   = lane >> 4;
    const uint32_t aRow = sbase + (uint32_t)(arow * 128);
    const uint32_t bRow = sbase + BOFFB + (uint32_t)(brow * 128);
    const int axr = arow & 7, bxr = brow & 7;

    for (int kc = 0; kc < G2_NC; ++kc) {
        cp_wait1();
        __syncthreads();

        const int s = kc % 3;
        const uint32_t aS = aRow + (uint32_t)(s * ASB);
        const uint32_t bS = bRow + (uint32_t)(s * ASB);
#pragma unroll
        for (int ksi = 0; ksi < 2; ++ksi) {
            const int c16 = (grp * 2 + ksi) * 2 + kl;
            const uint32_t swa = (uint32_t)((c16 ^ axr) << 4);
            const uint32_t swb = (uint32_t)((c16 ^ bxr) << 4);
            uint32_t a0[4], a1[4], b0[4], b1[4];
            ldsm_x4(a0, aS + swa);
            ldsm_x4(a1, aS + 16 * 128 + swa);
            ldsm_x4(b0, bS + swb);
            ldsm_x4(b1, bS + 16 * 128 + swb);
            mma16816(acc[0][0], a0, b0[0], b0[2]);
            mma16816(acc[0][1], a0, b0[1], b0[3]);
            mma16816(acc[0][2], a0, b1[0], b1[2]);
            mma16816(acc[0][3], a0, b1[1], b1[3]);
            mma16816(acc[1][0], a1, b0[0], b0[2]);
            mma16816(acc[1][1], a1, b0[1], b0[3]);
            mma16816(acc[1][2], a1, b1[0], b1[2]);
            mma16816(acc[1][3], a1, b1[1], b1[3]);
        }

        if (kc + 2 < G2_NC) {
            const int s2 = (kc + 2) % 3;
            const __half* Ag = Ab + (kc + 2) * BK + (size_t)lrow * KP2 + lcb * 8;
            const __half* Bg = Bb + (kc + 2) * BK + (size_t)lrow * KP2 + lcb * 8;
            const uint32_t rowA = sbase + s2 * ASB + lrow * 128;
            const uint32_t rowB = rowA + BOFFB;
#pragma unroll
            for (int q = 0; q < 2; ++q) {
                const uint32_t sw = (uint32_t)(((lcb + q) ^ lxr) << 4);
                cp_async16(rowA + sw, Ag + q * 8);
                cp_async16(rowB + sw, Bg + q * 8);
            }
        }
        cp_commit();
    }

    cp_wait0();
    __syncthreads();

    float* sC = (float*)smem;
    const int rr = lane >> 2;
    const int cc0 = wn * 32 + (lane & 3) * 2;

    if (grp == 1) {
#pragma unroll
        for (int mt = 0; mt < 2; ++mt)
#pragma unroll
            for (int j = 0; j < 4; ++j) {
                const int r0 = wm * 32 + rr + mt * 16;
                const int c  = cc0 + j * 8;
                float2 v0; v0.x = acc[mt][j][0]; v0.y = acc[mt][j][1];
                float2 v1; v1.x = acc[mt][j][2]; v1.y = acc[mt][j][3];
                *(float2*)(sC + r0 * SDP + c)       = v0;
                *(float2*)(sC + (r0 + 8) * SDP + c) = v1;
            }
    }
    __syncthreads();
    if (grp == 0) {
#pragma unroll
        for (int mt = 0; mt < 2; ++mt)
#pragma unroll
            for (int j = 0; j < 4; ++j) {
                const int r0 = wm * 32 + rr + mt * 16;
                const int c  = cc0 + j * 8;
                float2 p0 = *(float2*)(sC + r0 * SDP + c);
                float2 p1 = *(float2*)(sC + (r0 + 8) * SDP + c);
                p0.x += acc[mt][j][0]; p0.y += acc[mt][j][1];
                p1.x += acc[mt][j][2]; p1.y += acc[mt][j][3];
                *(float2*)(sC + r0 * SDP + c)       = p0;
                *(float2*)(sC + (r0 + 8) * SDP + c) = p1;
            }
    }
    __syncthreads();

    const float bv0 = bias[0], bv1 = bias[1];
    {
        const int r  = tid >> 2;
        const int cb = (tid & 3) * 16;
        float* dbase = outp + ((size_t)(bz * SEQ + m0 + r)) * NJC + n0;
#pragma unroll
        for (int e = 0; e < 8; ++e) {
            const int col = cb + e * 2;
            float2 v;
            v.x = sC[r * SDP + col] + bv0;
            v.y = sC[r * SDP + col + 1] + bv1;
            *(float2*)(dbase + col) = v;
        }
    }
    if (it != jt) {
        const int jl = tid >> 3;
        const int ql = tid & 7;
        const int j  = jt * 64 + half * 32 + jl;
        float* mbase = outp + ((size_t)(bz * SEQ + j)) * NJC + 2 * m0;
#pragma unroll
        for (int e = 0; e < 8; ++e) {
            const int q = ql + 8 * e;
            float2 s = *(float2*)(sC + q * SDP + 2 * jl);
            float2 v;
            v.x = s.x + bv0;
            v.y = s.y + bv1;
            *(float2*)(mbase + 2 * q) = v;
        }
    }
}

// ---------------------------------------------------------------------------
extern "C" void kernel_launch(void* const* d_in, const int* in_sizes, int n_in,
                              void* d_out, int out_size)
{
    const float* x  = (const float*)d_in[0];   // [4, 512, 1024]
    const float* W1 = (const float*)d_in[1];   // [256, 1024]
    const float* b1 = (const float*)d_in[2];   // [256]
    const float* W2 = (const float*)d_in[3];   // [2, 256]
    const float* b2 = (const float*)d_in[4];   // [2]
    float* out = (float*)d_out;                // [4, 512, 512, 2]

    // Prep: fp32 -> fp16 convert
    split_xw<<<2304, 256>>>(x, W1);

    // Stage 1 GEMM (full K=1024, fused o/A'/B' epilogue): grid 128 CTAs
    gemm1_kernel<<<dim3(HDIM / 64, MTOT / 64), 256, SMEM_SZ>>>(W2, b1);

    // Stage 2 GEMM (triangular): 36 pairs x 2 jc-halves x 4 batches = 288 CTAs
    gemm2_kernel<<<dim3(2, 36, BNUM), 256, SMEM_SZ>>>(b2, out);
}